// round 15
// baseline (speedup 1.0000x reference)
#include <cuda_runtime.h>
#include <cuda.h>
#include <cuda_bf16.h>
#include <math.h>
#include <stdint.h>

#define B_   256
#define S_   512
#define IN_  64
#define H_   1024
#define G4   4096
#define KTOT 1088
#define HEAD_ 128
#define OUT_ 64
#define KC   64
#define NCHUNK 17
#define UNITS 16
#define NCTA 128

#if defined(__CUDA_ARCH_FEAT_SM103_ALL) || defined(__CUDA_ARCH_FEAT_SM100_ALL) || \
    (defined(__CUDA_ARCH_SPECIFIC__) && (__CUDA_ARCH_SPECIFIC__ >= 1000))
#define HAS_TCGEN05 1
#else
#define HAS_TCGEN05 0
#endif

__device__ float g_c[B_ * H_];
__device__ __align__(1024) __nv_bfloat16 g_hall_hi[(size_t)(S_ + 1) * B_ * H_];
__device__ __align__(1024) __nv_bfloat16 g_hall_lo[(size_t)(S_ + 1) * B_ * H_];
__device__ __align__(1024) __nv_bfloat16 g_Wr_hi[(size_t)G4 * KTOT];  // rearranged gate-major
__device__ __align__(1024) __nv_bfloat16 g_Wr_lo[(size_t)G4 * KTOT];
__device__ __align__(1024) __nv_bfloat16 g_x_hi[(size_t)S_ * B_ * IN_];
__device__ __align__(1024) __nv_bfloat16 g_x_lo[(size_t)S_ * B_ * IN_];
__device__ __nv_bfloat16 g_Wd_hi[HEAD_ * H_];
__device__ __nv_bfloat16 g_Wd_lo[HEAD_ * H_];
__device__ __nv_bfloat16 g_W2_hi[OUT_ * HEAD_];
__device__ __nv_bfloat16 g_W2_lo[OUT_ * HEAD_];
__device__ unsigned g_sync_count;
__device__ unsigned g_sync_gen;

__device__ __forceinline__ float sigf(float x) { return 1.0f / (1.0f + __expf(-x)); }
__device__ __forceinline__ float tanhfast(float x) {
    return 2.0f / (1.0f + __expf(-2.0f * x)) - 1.0f;
}
__device__ __forceinline__ uint32_t smem_u32(const void* p) {
    return (uint32_t)__cvta_generic_to_shared(p);
}

__device__ __forceinline__ void grid_sync() {
    __syncthreads();
    if (threadIdx.x == 0) {
        __threadfence();
        unsigned gen;
        asm volatile("ld.acquire.gpu.global.u32 %0, [%1];" : "=r"(gen) : "l"(&g_sync_gen));
        unsigned arrived = atomicAdd(&g_sync_count, 1);
        if (arrived == NCTA - 1) {
            atomicExch(&g_sync_count, 0);
            __threadfence();
            atomicAdd(&g_sync_gen, 1);
        } else {
            unsigned cur;
            do {
                __nanosleep(20);
                asm volatile("ld.acquire.gpu.global.u32 %0, [%1];" : "=r"(cur) : "l"(&g_sync_gen));
            } while (cur == gen);
        }
        __threadfence();
    }
    __syncthreads();
}

#if HAS_TCGEN05
__device__ __forceinline__ uint64_t make_desc_sw128(uint32_t addr) {
    return 0x4000404000010000ULL | (uint64_t)((addr >> 4) & 0x3FFF);
}
__device__ __forceinline__ void mbar_init(uint32_t mbar, uint32_t cnt) {
    asm volatile("mbarrier.init.shared.b64 [%0], %1;" :: "r"(mbar), "r"(cnt) : "memory");
}
__device__ __forceinline__ void mbar_inval(uint32_t mbar) {
    asm volatile("mbarrier.inval.shared.b64 [%0];" :: "r"(mbar) : "memory");
}
__device__ __forceinline__ void mbar_wait(uint32_t mbar, uint32_t parity) {
    asm volatile(
        "{\n\t.reg .pred P1;\n\t"
        "WAIT_LOOP_%=:\n\t"
        "mbarrier.try_wait.parity.acquire.cta.shared::cta.b64 P1, [%0], %1, 0x989680;\n\t"
        "@P1 bra.uni WAIT_DONE_%=;\n\t"
        "bra.uni WAIT_LOOP_%=;\n\t"
        "WAIT_DONE_%=:\n\t}"
        :: "r"(mbar), "r"(parity) : "memory");
}
__device__ __forceinline__ void mbar_expect(uint32_t mbar, uint32_t bytes) {
    asm volatile("mbarrier.arrive.expect_tx.shared.b64 _, [%0], %1;"
                 :: "r"(mbar), "r"(bytes) : "memory");
}
__device__ __forceinline__ void tmem_alloc(uint32_t smem_res, uint32_t ncols) {
    asm volatile("tcgen05.alloc.cta_group::1.sync.aligned.shared::cta.b32 [%0], %1;"
                 :: "r"(smem_res), "r"(ncols) : "memory");
}
__device__ __forceinline__ void tmem_dealloc(uint32_t tmem, uint32_t ncols) {
    asm volatile("tcgen05.dealloc.cta_group::1.sync.aligned.b32 %0, %1;" :: "r"(tmem), "r"(ncols));
}
__device__ __forceinline__ void tmem_relinquish() {
    asm volatile("tcgen05.relinquish_alloc_permit.cta_group::1.sync.aligned;");
}
__device__ __forceinline__ void tc_commit(uint32_t mbar) {
    asm volatile("tcgen05.commit.cta_group::1.mbarrier::arrive::one.shared::cluster.b64 [%0];"
                 :: "r"(mbar) : "memory");
}
__device__ __forceinline__ void tc_commit_mc(uint32_t mbar, uint16_t mask) {
    asm volatile(
        "tcgen05.commit.cta_group::1.mbarrier::arrive::one.shared::cluster.multicast::cluster.b64 [%0], %1;"
        :: "r"(mbar), "h"(mask) : "memory");
}
__device__ __forceinline__ void tc_fence_after() {
    asm volatile("tcgen05.fence::after_thread_sync;" ::: "memory");
}
__device__ __forceinline__ void tc_fence_before() {
    asm volatile("tcgen05.fence::before_thread_sync;" ::: "memory");
}
__device__ __forceinline__ void tc_wait_ld() {
    asm volatile("tcgen05.wait::ld.sync.aligned;" ::: "memory");
}
__device__ __forceinline__ void fence_proxy_async_shared() {
    asm volatile("fence.proxy.async.shared::cta;" ::: "memory");
}
__device__ __forceinline__ void mma_f16_ss(uint32_t d_tmem, uint64_t a_desc, uint64_t b_desc,
                                           uint32_t idesc, uint32_t enable) {
    asm volatile(
        "{\n\t.reg .pred p;\n\t"
        "setp.ne.u32 p, %4, 0;\n\t"
        "tcgen05.mma.cta_group::1.kind::f16 [%0], %1, %2, %3, {%5, %5, %5, %5}, p;\n\t}"
        :: "r"(d_tmem), "l"(a_desc), "l"(b_desc), "r"(idesc), "r"(enable), "r"(0u)
        : "memory");
}
__device__ __forceinline__ void tma_mc(uint32_t dst, const CUtensorMap* m, int cx, int cy,
                                       uint32_t mbar, uint16_t mask) {
    asm volatile(
        "cp.async.bulk.tensor.2d.shared::cluster.global.tile.mbarrier::complete_tx::bytes.multicast::cluster "
        "[%0], [%1, {%2, %3}], [%4], %5;"
        :: "r"(dst), "l"(m), "r"(cx), "r"(cy), "r"(mbar), "h"(mask) : "memory");
}
__device__ __forceinline__ void cp16(uint32_t dst, const void* src) {
    asm volatile("cp.async.cg.shared.global [%0], [%1], 16;" :: "r"(dst), "l"(src));
}
__device__ __forceinline__ void cp_commit() {
    asm volatile("cp.async.commit_group;" ::: "memory");
}
#define CP_WAIT_GROUP(n) asm volatile("cp.async.wait_group %0;" :: "n"(n) : "memory")
#define CLUSTER_SYNC_() do { \
    asm volatile("barrier.cluster.arrive.aligned;" ::: "memory"); \
    asm volatile("barrier.cluster.wait.aligned;" ::: "memory"); \
} while (0)
#define TC_LD_X16(r, tmem_addr) \
    asm volatile( \
        "tcgen05.ld.sync.aligned.32x32b.x16.b32 " \
        "{%0, %1, %2, %3, %4, %5, %6, %7, " \
        " %8, %9, %10, %11, %12, %13, %14, %15}, [%16];" \
        : "=r"((r)[0]),  "=r"((r)[1]),  "=r"((r)[2]),  "=r"((r)[3]), \
          "=r"((r)[4]),  "=r"((r)[5]),  "=r"((r)[6]),  "=r"((r)[7]), \
          "=r"((r)[8]),  "=r"((r)[9]),  "=r"((r)[10]), "=r"((r)[11]), \
          "=r"((r)[12]), "=r"((r)[13]), "=r"((r)[14]), "=r"((r)[15]) \
        : "r"(tmem_addr))
#define TC_LD_X32(r, tmem_addr) \
    asm volatile( \
        "tcgen05.ld.sync.aligned.32x32b.x32.b32 " \
        "{%0, %1, %2, %3, %4, %5, %6, %7, " \
        " %8, %9, %10, %11, %12, %13, %14, %15, " \
        " %16, %17, %18, %19, %20, %21, %22, %23, " \
        " %24, %25, %26, %27, %28, %29, %30, %31}, [%32];" \
        : "=r"((r)[0]),  "=r"((r)[1]),  "=r"((r)[2]),  "=r"((r)[3]), \
          "=r"((r)[4]),  "=r"((r)[5]),  "=r"((r)[6]),  "=r"((r)[7]), \
          "=r"((r)[8]),  "=r"((r)[9]),  "=r"((r)[10]), "=r"((r)[11]), \
          "=r"((r)[12]), "=r"((r)[13]), "=r"((r)[14]), "=r"((r)[15]), \
          "=r"((r)[16]), "=r"((r)[17]), "=r"((r)[18]), "=r"((r)[19]), \
          "=r"((r)[20]), "=r"((r)[21]), "=r"((r)[22]), "=r"((r)[23]), \
          "=r"((r)[24]), "=r"((r)[25]), "=r"((r)[26]), "=r"((r)[27]), \
          "=r"((r)[28]), "=r"((r)[29]), "=r"((r)[30]), "=r"((r)[31]) \
        : "r"(tmem_addr))
#endif  // HAS_TCGEN05

#define IDESC_N128 ((1u << 4) | (1u << 7) | (1u << 10) | (16u << 17) | (8u << 24))
#define IDESC_N64  ((1u << 4) | (1u << 7) | (1u << 10) | (8u << 17)  | (8u << 24))

// LSTM stage: A 128x64 hi/lo (16+16KB) + W 64x64 hi/lo (8+8KB) = 48KB; 4 stages
#define LSTG 49152
#define L_A_HI 0
#define L_A_LO 16384
#define L_B_HI 32768
#define L_B_LO 40960
#define NST 4
#define SMEM_LSTM (1024 + NST * LSTG)

// head kernel layout (R9, passing)
#define STAGE_BYTES 65536
#define OFF_A_HI 0
#define OFF_A_LO 16384
#define OFF_B_HI 32768
#define OFF_B_LO 49152
#define HW2_BASE   1024
#define HSTAGE0    33792
#define SMEM_HEAD  (HSTAGE0 + 3 * STAGE_BYTES)

// ---------------- prep ----------------
__global__ void prep_misc(const float* __restrict__ Wd, const float* __restrict__ W2) {
    for (int i = blockIdx.x * blockDim.x + threadIdx.x; i < B_ * H_;
         i += gridDim.x * blockDim.x) {
        g_c[i] = 0.f;
        g_hall_hi[i] = __float2bfloat16(0.f);
        g_hall_lo[i] = __float2bfloat16(0.f);
        if (i < HEAD_ * H_) {
            float v = Wd[i];
            __nv_bfloat16 hi = __float2bfloat16(v);
            g_Wd_hi[i] = hi;
            g_Wd_lo[i] = __float2bfloat16(v - __bfloat162float(hi));
        }
        if (i < OUT_ * HEAD_) {
            float v = W2[i];
            __nv_bfloat16 hi = __float2bfloat16(v);
            g_W2_hi[i] = hi;
            g_W2_lo[i] = __float2bfloat16(v - __bfloat162float(hi));
        }
        if (i == 0) { g_sync_count = 0; g_sync_gen = 0; }
    }
}
// rearranged weights: row' = ntile*64 + gate*16 + unit  <-  orig row gate*1024 + ntile*16 + unit
__global__ void prep_w(const float* __restrict__ Wih, const float* __restrict__ Whh) {
    const size_t n = (size_t)G4 * KTOT;
    for (size_t i = blockIdx.x * blockDim.x + threadIdx.x; i < n;
         i += (size_t)gridDim.x * blockDim.x) {
        int rp = (int)(i / KTOT);
        int k = (int)(i - (size_t)rp * KTOT);
        int ntile = rp >> 6;
        int g = (rp & 63) >> 4;
        int u = rp & 15;
        int orow = (g << 10) + (ntile << 4) + u;
        float v = (k < IN_) ? Wih[(size_t)orow * IN_ + k] : Whh[(size_t)orow * H_ + (k - IN_)];
        __nv_bfloat16 hi = __float2bfloat16(v);
        g_Wr_hi[i] = hi;
        g_Wr_lo[i] = __float2bfloat16(v - __bfloat162float(hi));
    }
}
__global__ void prep_x(const float* __restrict__ x) {
    const size_t n = (size_t)S_ * B_ * IN_;
    for (size_t i = blockIdx.x * blockDim.x + threadIdx.x; i < n;
         i += (size_t)gridDim.x * blockDim.x) {
        int t = (int)(i / (B_ * IN_));
        int rem = (int)(i - (size_t)t * (B_ * IN_));
        int b = rem / IN_;
        int ii = rem - b * IN_;
        float v = x[((size_t)b * S_ + t) * IN_ + ii];
        __nv_bfloat16 hi = __float2bfloat16(v);
        g_x_hi[i] = hi;
        g_x_lo[i] = __float2bfloat16(v - __bfloat162float(hi));
    }
}

// ---------------- persistent LSTM: 128 CTAs in clusters of 4 (2M x 2N), TMA multicast ----
__global__ void __launch_bounds__(256, 1) __cluster_dims__(4, 1, 1) lstm_persist(
    const float* __restrict__ bih, const float* __restrict__ bhh,
    const __grid_constant__ CUtensorMap mXh, const __grid_constant__ CUtensorMap mXl,
    const __grid_constant__ CUtensorMap mAh, const __grid_constant__ CUtensorMap mAl,
    const __grid_constant__ CUtensorMap mWh, const __grid_constant__ CUtensorMap mWl)
{
#if HAS_TCGEN05
    extern __shared__ char smem[];
    const uint32_t sb = smem_u32(smem);
    const int tid = threadIdx.x;
    const int wid = tid >> 5;
    const int lane = tid & 31;
    const int rank = blockIdx.x & 3;
    const int bm0 = (rank & 1) * 128;
    const int ntile = (blockIdx.x >> 2) * 2 + (rank >> 1);
    const int j0 = ntile * UNITS;

    if (wid == 0) { tmem_alloc(sb, 128); tmem_relinquish(); }
    if (tid == 0) {
#pragma unroll
        for (int s = 0; s < NST; s++) {
            mbar_init(sb + 8 + 8 * s, 1);          // full[s]: 1 expect_tx arrive
            mbar_init(sb + 40 + 8 * s, 4);         // empty[s]: 4 multicast commits
        }
    }
    if (tid < 64) {
        int grow = ((tid >> 4) << 10) + j0 + (tid & 15);
        ((float*)(smem + 256))[tid] = bih[grow] + bhh[grow];
    }
    __syncthreads();
    CLUSTER_SYNC_();
    const uint32_t tmem = *(const uint32_t*)smem;

    uint64_t dAh[NST], dAl[NST], dBh[NST], dBl[NST];
#pragma unroll
    for (int s = 0; s < NST; s++) {
        uint32_t st = sb + 1024 + s * LSTG;
        dAh[s] = make_desc_sw128(st + L_A_HI);
        dAl[s] = make_desc_sw128(st + L_A_LO);
        dBh[s] = make_desc_sw128(st + L_B_HI);
        dBl[s] = make_desc_sw128(st + L_B_LO);
    }

    // tid0-only: expect own 48KB + issue role-assigned multicast loads
    auto issue_load = [&](int cn, int sl, int tt) {
        const uint32_t st = sb + 1024 + sl * LSTG;
        const uint32_t fm = sb + 8 + 8 * sl;
        mbar_expect(fm, 49152);
        if (rank == 1 || rank == 2) {
            const uint16_t mask = (rank == 1) ? 0xA : 0x5;
            if (cn == 0) {
                tma_mc(st + L_A_HI, &mXh, 0, tt * B_ + bm0, fm, mask);
                tma_mc(st + L_A_LO, &mXl, 0, tt * B_ + bm0, fm, mask);
            } else {
                tma_mc(st + L_A_HI, &mAh, (cn - 1) * KC, tt * B_ + bm0, fm, mask);
                tma_mc(st + L_A_LO, &mAl, (cn - 1) * KC, tt * B_ + bm0, fm, mask);
            }
        } else {
            const uint16_t mask = (rank == 0) ? 0x3 : 0xC;
            tma_mc(st + L_B_HI, &mWh, cn * KC, ntile * 64, fm, mask);
            tma_mc(st + L_B_LO, &mWl, cn * KC, ntile * 64, fm, mask);
        }
    };

    uint32_t pf[NST] = {0, 0, 0, 0};   // full parity (tid0, phase-exact)
    uint32_t pe[NST] = {0, 0, 0, 0};   // empty parity (tid0 is the only waiter)

    for (int t = 0; t < S_; t++) {
        if (t == 0 && tid == 0) {
            issue_load(0, 0, 0); issue_load(1, 1, 0); issue_load(2, 2, 0);
        }
#pragma unroll
        for (int ck = 0; ck < NCHUNK; ck++) {
            const int s = ck & 3;
            if (tid == 0) {
                mbar_wait(sb + 8 + 8 * s, pf[s]); pf[s] ^= 1;
#pragma unroll
                for (int k4 = 0; k4 < 4; k4++) {
                    uint32_t en0 = (ck > 0 || k4 > 0) ? 1u : 0u;
                    mma_f16_ss(tmem, dAh[s] + k4 * 2, dBh[s] + k4 * 2, IDESC_N64, en0);
                    mma_f16_ss(tmem, dAh[s] + k4 * 2, dBl[s] + k4 * 2, IDESC_N64, 1u);
                    mma_f16_ss(tmem, dAl[s] + k4 * 2, dBh[s] + k4 * 2, IDESC_N64, 1u);
                }
                tc_commit_mc(sb + 40 + 8 * s, 0xF);
            }
            const int cn = ck + 3;
            if (cn <= NCHUNK - 1) {
                const int sl = cn & 3;
                if (cn >= 4) {
                    if (tid == 0) mbar_wait(sb + 40 + 8 * sl, pe[sl]);
                    pe[sl] ^= 1;
                }
                if (tid == 0) issue_load(cn, sl, t);
            }
        }
        // drain: ONLY tid0 (phase-exact parity) waits chunk16's 4 commits; others
        // are released by the barrier. (R14 let all 256 threads parity-wait here,
        // which aliases phases for lagging threads -> stale TMEM reads.)
        if (tid == 0) mbar_wait(sb + 40, pe[0]);
        pe[0] ^= 1;
        pe[1] ^= 1; pe[2] ^= 1; pe[3] ^= 1;   // chunks 13,14,15 commits, unconsumed
        __syncthreads();
        tc_fence_after();

        if (t + 1 < S_ && tid == 0) issue_load(0, 0, t + 1);   // x-only, stage0 free

        // ---- epilogue: 4 warps x 32 rows, 16 units ----
        if (wid < 4) {
            const int brow = bm0 + wid * 32 + lane;
            const int cbase = brow * H_ + j0;
            const size_t hbase = ((size_t)(t + 1) * B_ + brow) * H_ + j0;
            const float* bs = (const float*)(smem + 256);
            uint32_t ri[16], rf[16], rg[16], ro[16];
            TC_LD_X16(ri, tmem + 0);
            TC_LD_X16(rf, tmem + 16);
            TC_LD_X16(rg, tmem + 32);
            TC_LD_X16(ro, tmem + 48);
            tc_wait_ld();

            float cold[16];
#pragma unroll
            for (int v = 0; v < 4; v++)
                *(float4*)&cold[v * 4] = *(const float4*)(g_c + cbase + v * 4);

            float cnv[16], hnv[16];
#pragma unroll
            for (int u = 0; u < 16; u++) {
                float ig = __uint_as_float(ri[u]) + bs[u];
                float fg = __uint_as_float(rf[u]) + bs[16 + u];
                float gg = __uint_as_float(rg[u]) + bs[32 + u];
                float og = __uint_as_float(ro[u]) + bs[48 + u];
                float cn = sigf(fg) * cold[u] + sigf(ig) * tanhfast(gg);
                cnv[u] = cn;
                hnv[u] = sigf(og) * tanhfast(cn);
            }
#pragma unroll
            for (int v = 0; v < 4; v++)
                *(float4*)(g_c + cbase + v * 4) =
                    make_float4(cnv[v * 4], cnv[v * 4 + 1], cnv[v * 4 + 2], cnv[v * 4 + 3]);
            uint32_t hp[8], lp[8];
#pragma unroll
            for (int v = 0; v < 8; v++) {
                __nv_bfloat16 h0 = __float2bfloat16(hnv[v * 2]);
                __nv_bfloat16 h1 = __float2bfloat16(hnv[v * 2 + 1]);
                __nv_bfloat16 l0 = __float2bfloat16(hnv[v * 2] - __bfloat162float(h0));
                __nv_bfloat16 l1 = __float2bfloat16(hnv[v * 2 + 1] - __bfloat162float(h1));
                hp[v] = ((uint32_t)__bfloat16_as_ushort(h1) << 16) | __bfloat16_as_ushort(h0);
                lp[v] = ((uint32_t)__bfloat16_as_ushort(l1) << 16) | __bfloat16_as_ushort(l0);
            }
            *(uint4*)(&g_hall_hi[hbase])     = make_uint4(hp[0], hp[1], hp[2], hp[3]);
            *(uint4*)(&g_hall_hi[hbase + 8]) = make_uint4(hp[4], hp[5], hp[6], hp[7]);
            *(uint4*)(&g_hall_lo[hbase])     = make_uint4(lp[0], lp[1], lp[2], lp[3]);
            *(uint4*)(&g_hall_lo[hbase + 8]) = make_uint4(lp[4], lp[5], lp[6], lp[7]);
            tc_fence_before();
        }

        if (t + 1 < S_) {
            grid_sync();
            if (tid == 0) { issue_load(1, 1, t + 1); issue_load(2, 2, t + 1); }
        } else {
            __syncthreads();
        }
    }

    __syncthreads();
    CLUSTER_SYNC_();
    if (tid == 0) {
#pragma unroll
        for (int s = 0; s < NST; s++) { mbar_inval(sb + 8 + 8 * s); mbar_inval(sb + 40 + 8 * s); }
    }
    __syncthreads();
    if (wid == 0) tmem_dealloc(tmem, 128);
    CLUSTER_SYNC_();
#else
    // correct SIMT fallback (never runs on GB300)
    const int tid = threadIdx.x;
    const int rank = blockIdx.x & 3;
    const int bm0 = (rank & 1) * 128;
    const int ntile = (blockIdx.x >> 2) * 2 + (rank >> 1);
    const int j0 = ntile * UNITS;
    for (int t = 0; t < S_; t++) {
        for (int o = tid; o < 128 * UNITS; o += 256) {
            int row = o / UNITS, u = o % UNITS;
            int b = bm0 + row, jg = j0 + u;
            float acc[4] = {0.f, 0.f, 0.f, 0.f};
            for (int k = 0; k < KTOT; k++) {
                float a;
                if (k < IN_) {
                    size_t xo = ((size_t)t * B_ + b) * IN_ + k;
                    a = __bfloat162float(g_x_hi[xo]) + __bfloat162float(g_x_lo[xo]);
                } else {
                    size_t ho = ((size_t)t * B_ + b) * H_ + (k - IN_);
                    a = __bfloat162float(g_hall_hi[ho]) + __bfloat162float(g_hall_lo[ho]);
                }
#pragma unroll
                for (int g = 0; g < 4; g++) {
                    size_t wi = (size_t)(ntile * 64 + g * 16 + u) * KTOT + k;
                    acc[g] += a * (__bfloat162float(g_Wr_hi[wi]) + __bfloat162float(g_Wr_lo[wi]));
                }
            }
            float ig = acc[0] + bih[jg] + bhh[jg];
            float fg = acc[1] + bih[H_ + jg] + bhh[H_ + jg];
            float gg = acc[2] + bih[2 * H_ + jg] + bhh[2 * H_ + jg];
            float og = acc[3] + bih[3 * H_ + jg] + bhh[3 * H_ + jg];
            int idx = b * H_ + jg;
            float cn = sigf(fg) * g_c[idx] + sigf(ig) * tanhfast(gg);
            float hn = sigf(og) * tanhfast(cn);
            g_c[idx] = cn;
            size_t hb = ((size_t)(t + 1) * B_ + b) * H_ + jg;
            __nv_bfloat16 hh = __float2bfloat16(hn);
            g_hall_hi[hb] = hh;
            g_hall_lo[hb] = __float2bfloat16(hn - __bfloat162float(hh));
        }
        grid_sync();
    }
#endif
}

// ---------------- fused tcgen05 dense head (R9, passing) ----------------
__global__ void __launch_bounds__(256, 1) head_tc(
    const float* __restrict__ bd, const float* __restrict__ b2, float* __restrict__ out)
{
#if HAS_TCGEN05
    extern __shared__ char smem[];
    const uint32_t sb = smem_u32(smem);
    const int tid = threadIdx.x;
    const int wid = tid >> 5;
    const int lane = tid & 31;
    const int r0 = blockIdx.x * 128;

    if (wid == 0) { tmem_alloc(sb, 256); tmem_relinquish(); }
    if (tid == 0) { mbar_init(sb + 8, 1); mbar_init(sb + 16, 1); mbar_init(sb + 24, 1); }
    if (tid < 128) ((float*)(smem + 256))[tid] = bd[tid];
    if (tid < 64)  ((float*)(smem + 768))[tid] = b2[tid];
    for (int i = tid; i < 64 * 16; i += 256) {
        int row = i >> 4;
        int col = (i & 15) * 8;
        int chunk = col >> 6, kin = col & 63;
        uint32_t off = row * 128 + kin * 2;
        uint32_t sw = off ^ ((off >> 3) & 0x70);
        *(uint4*)(smem + HW2_BASE + chunk * 8192 + sw) =
            *(const uint4*)(g_W2_hi + row * HEAD_ + col);
        *(uint4*)(smem + HW2_BASE + 16384 + chunk * 8192 + sw) =
            *(const uint4*)(g_W2_lo + row * HEAD_ + col);
    }
    __syncthreads();
    const uint32_t tmem = *(const uint32_t*)smem;

    auto load_chunk = [&](int cn, int buf) {
        const uint32_t st = sb + HSTAGE0 + buf * STAGE_BYTES;
#pragma unroll
        for (int q = 0; q < 4; q++) {
            int slot = tid + q * 256;
            int row = slot >> 3, cc = slot & 7;
            uint32_t off = row * 128 + cc * 16;
            uint32_t sw = off ^ ((off >> 3) & 0x70);
            size_t oa = ((size_t)(B_ + r0 + row)) * H_ + cn * KC + cc * 8;
            cp16(st + OFF_A_HI + sw, g_hall_hi + oa);
            cp16(st + OFF_A_LO + sw, g_hall_lo + oa);
            size_t ob = (size_t)row * H_ + cn * KC + cc * 8;
            cp16(st + OFF_B_HI + sw, g_Wd_hi + ob);
            cp16(st + OFF_B_LO + sw, g_Wd_lo + ob);
        }
        cp_commit();
    };

    uint32_t wp[3] = {0, 0, 0};
    load_chunk(0, 0);
    load_chunk(1, 1);
#pragma unroll
    for (int ck = 0; ck < 16; ck++) {
        const int cn = ck + 2;
        if (cn <= 15) {
            const int b = cn % 3;
            if (cn >= 3) { mbar_wait(sb + 8 + 8 * b, wp[b]); wp[b] ^= 1; }
            load_chunk(cn, b);
        }
        if (ck <= 13)      CP_WAIT_GROUP(2);
        else if (ck == 14) CP_WAIT_GROUP(1);
        else               CP_WAIT_GROUP(0);
        __syncthreads();
        if (tid == 0) {
            const uint32_t st = sb + HSTAGE0 + (ck % 3) * STAGE_BYTES;
            fence_proxy_async_shared();
            uint64_t dAh = make_desc_sw128(st + OFF_A_HI);
            uint64_t dAl = make_desc_sw128(st + OFF_A_LO);
            uint64_t dBh = make_desc_sw128(st + OFF_B_HI);
            uint64_t dBl = make_desc_sw128(st + OFF_B_LO);
#pragma unroll
            for (int k4 = 0; k4 < 4; k4++) {
                uint32_t en0 = (ck > 0 || k4 > 0) ? 1u : 0u;
                mma_f16_ss(tmem, dAh + k4 * 2, dBh + k4 * 2, IDESC_N128, en0);
                mma_f16_ss(tmem, dAh + k4 * 2, dBl + k4 * 2, IDESC_N128, 1u);
                mma_f16_ss(tmem, dAl + k4 * 2, dBh + k4 * 2, IDESC_N128, 1u);
            }
            tc_commit(sb + 8 + 8 * (ck % 3));
        }
    }
    mbar_wait(sb + 8, wp[0]); wp[0] ^= 1;
    wp[1] ^= 1; wp[2] ^= 1;
    tc_fence_after();

    if (wid < 4) {
        const int rowl = wid * 32 + lane;
        const float* bds = (const float*)(smem + 256);
#pragma unroll
        for (int cb = 0; cb < 4; cb++) {
            uint32_t r[32];
            TC_LD_X32(r, tmem + cb * 32);
            tc_wait_ld();
#pragma unroll
            for (int c = 0; c < 32; c++) {
                int col = cb * 32 + c;
                float v = __uint_as_float(r[c]) + bds[col];
                v = fmaxf(v, 0.f);
                __nv_bfloat16 hi = __float2bfloat16(v);
                __nv_bfloat16 lo = __float2bfloat16(v - __bfloat162float(hi));
                int chunk = col >> 6, kin = col & 63;
                uint32_t off = rowl * 128 + kin * 2;
                uint32_t sw = off ^ ((off >> 3) & 0x70);
                *(__nv_bfloat16*)(smem + HSTAGE0 + chunk * 16384 + sw) = hi;
                *(__nv_bfloat16*)(smem + HSTAGE0 + 32768 + chunk * 16384 + sw) = lo;
            }
        }
        tc_fence_before();
    }
    __syncthreads();

    if (tid == 0) {
        fence_proxy_async_shared();
#pragma unroll
        for (int c = 0; c < 2; c++) {
            uint64_t dPh = make_desc_sw128(sb + HSTAGE0 + c * 16384);
            uint64_t dPl = make_desc_sw128(sb + HSTAGE0 + 32768 + c * 16384);
            uint64_t dWh = make_desc_sw128(sb + HW2_BASE + c * 8192);
            uint64_t dWl = make_desc_sw128(sb + HW2_BASE + 16384 + c * 8192);
#pragma unroll
            for (int k4 = 0; k4 < 4; k4++) {
                uint32_t en0 = (c > 0 || k4 > 0) ? 1u : 0u;
                mma_f16_ss(tmem + 128, dPh + k4 * 2, dWh + k4 * 2, IDESC_N64, en0);
                mma_f16_ss(tmem + 128, dPh + k4 * 2, dWl + k4 * 2, IDESC_N64, 1u);
                mma_f16_ss(tmem + 128, dPl + k4 * 2, dWh + k4 * 2, IDESC_N64, 1u);
            }
        }
        tc_commit(sb + 8);
    }
    mbar_wait(sb + 8, wp[0]); wp[0] ^= 1;
    tc_fence_after();

    if (wid < 4) {
        uint32_t d[64];
        TC_LD_X32(d, tmem + 128);
        TC_LD_X32(d + 32, tmem + 160);
        tc_wait_ld();
        tc_fence_before();
        const float* b2s = (const float*)(smem + 768);
        int r = r0 + wid * 32 + lane;
        int tt = r >> 8;
        int b = r & 255;
        float* op = out + ((size_t)b * S_ + tt) * OUT_;
#pragma unroll
        for (int v = 0; v < 16; v++) {
            *(float4*)(op + v * 4) = make_float4(
                __uint_as_float(d[v * 4 + 0]) + b2s[v * 4 + 0],
                __uint_as_float(d[v * 4 + 1]) + b2s[v * 4 + 1],
                __uint_as_float(d[v * 4 + 2]) + b2s[v * 4 + 2],
                __uint_as_float(d[v * 4 + 3]) + b2s[v * 4 + 3]);
        }
    }
    __syncthreads();
    if (tid == 0) { mbar_inval(sb + 8); mbar_inval(sb + 16); mbar_inval(sb + 24); }
    __syncthreads();
    if (wid == 0) tmem_dealloc(tmem, 256);
#else
    const int tid = threadIdx.x;
    const int r0 = blockIdx.x * 128;
    for (int rl = tid; rl < 128; rl += 256) {
        int r = r0 + rl;
        float p[HEAD_];
        for (int n = 0; n < HEAD_; n++) {
            float acc = bd[n];
            for (int k = 0; k < H_; k++) {
                size_t ho = ((size_t)(B_ + r)) * H_ + k;
                float hv = __bfloat162float(g_hall_hi[ho]) + __bfloat162float(g_hall_lo[ho]);
                float wv = __bfloat162float(g_Wd_hi[n * H_ + k]) +
                           __bfloat162float(g_Wd_lo[n * H_ + k]);
                acc += hv * wv;
            }
            p[n] = acc > 0.f ? acc : 0.f;
        }
        int tt = r >> 8, b = r & 255;
        for (int n = 0; n < OUT_; n++) {
            float acc = b2[n];
            for (int k = 0; k < HEAD_; k++) {
                float wv = __bfloat162float(g_W2_hi[n * HEAD_ + k]) +
                           __bfloat162float(g_W2_lo[n * HEAD_ + k]);
                acc += p[k] * wv;
            }
            out[((size_t)b * S_ + tt) * OUT_ + n] = acc;
        }
    }
#endif
}

// ---------------- host: tensormap building + launch ----------------
typedef CUresult (*EncodeFn)(CUtensorMap*, CUtensorMapDataType, cuuint32_t, void*,
    const cuuint64_t*, const cuuint64_t*, const cuuint32_t*, const cuuint32_t*,
    CUtensorMapInterleave, CUtensorMapSwizzle, CUtensorMapL2promotion, CUtensorMapFloatOOBfill);

static void make_map2d(EncodeFn enc, CUtensorMap* m, void* base, uint64_t d0, uint64_t d1,
                       uint64_t stride1, uint32_t b0, uint32_t b1) {
    cuuint64_t dims[2] = {d0, d1};
    cuuint64_t strides[1] = {stride1};
    cuuint32_t box[2] = {b0, b1};
    cuuint32_t es[2] = {1, 1};
    enc(m, CU_TENSOR_MAP_DATA_TYPE_BFLOAT16, 2, base, dims, strides, box, es,
        CU_TENSOR_MAP_INTERLEAVE_NONE, CU_TENSOR_MAP_SWIZZLE_128B,
        CU_TENSOR_MAP_L2_PROMOTION_L2_128B, CU_TENSOR_MAP_FLOAT_OOB_FILL_NONE);
}

extern "C" void kernel_launch(void* const* d_in, const int* in_sizes, int n_in,
                              void* d_out, int out_size)
{
    const float* x   = (const float*)d_in[0];
    const float* Wih = (const float*)d_in[1];
    const float* bih = (const float*)d_in[2];
    const float* Whh = (const float*)d_in[3];
    const float* bhh = (const float*)d_in[4];
    const float* Wd  = (const float*)d_in[5];
    const float* bd  = (const float*)d_in[6];
    const float* W2  = (const float*)d_in[7];
    const float* b2  = (const float*)d_in[8];
    float* out = (float*)d_out;

    cudaFuncSetAttribute(lstm_persist, cudaFuncAttributeMaxDynamicSharedMemorySize, SMEM_LSTM);
    cudaFuncSetAttribute(head_tc, cudaFuncAttributeMaxDynamicSharedMemorySize, SMEM_HEAD);

    EncodeFn enc = nullptr;
    {
        void* p = nullptr;
        cudaDriverEntryPointQueryResult qr;
        cudaGetDriverEntryPoint("cuTensorMapEncodeTiled", &p, cudaEnableDefault, &qr);
        enc = (EncodeFn)p;
    }
    void *pXh, *pXl, *pAh, *pAl, *pWh, *pWl;
    cudaGetSymbolAddress(&pXh, g_x_hi);
    cudaGetSymbolAddress(&pXl, g_x_lo);
    cudaGetSymbolAddress(&pAh, g_hall_hi);
    cudaGetSymbolAddress(&pAl, g_hall_lo);
    cudaGetSymbolAddress(&pWh, g_Wr_hi);
    cudaGetSymbolAddress(&pWl, g_Wr_lo);

    CUtensorMap mXh, mXl, mAh, mAl, mWh, mWl;
    make_map2d(enc, &mXh, pXh, IN_, (uint64_t)S_ * B_, IN_ * 2, 64, 128);
    make_map2d(enc, &mXl, pXl, IN_, (uint64_t)S_ * B_, IN_ * 2, 64, 128);
    make_map2d(enc, &mAh, pAh, H_, (uint64_t)(S_ + 1) * B_, H_ * 2, 64, 128);
    make_map2d(enc, &mAl, pAl, H_, (uint64_t)(S_ + 1) * B_, H_ * 2, 64, 128);
    make_map2d(enc, &mWh, pWh, KTOT, G4, KTOT * 2, 64, 64);
    make_map2d(enc, &mWl, pWl, KTOT, G4, KTOT * 2, 64, 64);

    prep_misc<<<512, 256>>>(Wd, W2);
    prep_w<<<512, 256>>>(Wih, Whh);
    prep_x<<<512, 256>>>(x);

    lstm_persist<<<NCTA, 256, SMEM_LSTM>>>(bih, bhh, mXh, mXl, mAh, mAl, mWh, mWl);
    head_tc<<<(S_ * B_) / 128, 256, SMEM_HEAD>>>(bd, b2, out);
}

// round 16
// speedup vs baseline: 1.0487x; 1.0487x over previous
#include <cuda_runtime.h>
#include <cuda.h>
#include <cuda_bf16.h>
#include <math.h>
#include <stdint.h>

#define B_   256
#define S_   512
#define IN_  64
#define H_   1024
#define G4   4096
#define KTOT 1088
#define HEAD_ 128
#define OUT_ 64
#define KC   64
#define NCHUNK 17
#define UNITS 16
#define NCTA 128

#if defined(__CUDA_ARCH_FEAT_SM103_ALL) || defined(__CUDA_ARCH_FEAT_SM100_ALL) || \
    (defined(__CUDA_ARCH_SPECIFIC__) && (__CUDA_ARCH_SPECIFIC__ >= 1000))
#define HAS_TCGEN05 1
#else
#define HAS_TCGEN05 0
#endif

__device__ float g_c[B_ * H_];   // used only by the non-'a' fallback path
__device__ __align__(1024) __nv_bfloat16 g_hall_hi[(size_t)(S_ + 1) * B_ * H_];
__device__ __align__(1024) __nv_bfloat16 g_hall_lo[(size_t)(S_ + 1) * B_ * H_];
__device__ __align__(1024) __nv_bfloat16 g_Wr_hi[(size_t)G4 * KTOT];  // gate-major rearranged
__device__ __align__(1024) __nv_bfloat16 g_Wr_lo[(size_t)G4 * KTOT];
__device__ __align__(1024) __nv_bfloat16 g_x_hi[(size_t)S_ * B_ * IN_];
__device__ __align__(1024) __nv_bfloat16 g_x_lo[(size_t)S_ * B_ * IN_];
__device__ __nv_bfloat16 g_Wd_hi[HEAD_ * H_];
__device__ __nv_bfloat16 g_Wd_lo[HEAD_ * H_];
__device__ __nv_bfloat16 g_W2_hi[OUT_ * HEAD_];
__device__ __nv_bfloat16 g_W2_lo[OUT_ * HEAD_];
__device__ unsigned g_sync_count;
__device__ unsigned g_sync_gen;
__device__ unsigned g_arr[NCTA * 32];   // distributed arrival flags (padded lines)
__device__ unsigned g_rel;

__device__ __forceinline__ float sigf(float x) { return 1.0f / (1.0f + __expf(-x)); }
__device__ __forceinline__ float tanhfast(float x) {
    return 2.0f / (1.0f + __expf(-2.0f * x)) - 1.0f;
}
__device__ __forceinline__ uint32_t smem_u32(const void* p) {
    return (uint32_t)__cvta_generic_to_shared(p);
}

// old single-counter barrier (fallback path only)
__device__ __forceinline__ void grid_sync() {
    __syncthreads();
    if (threadIdx.x == 0) {
        __threadfence();
        unsigned gen;
        asm volatile("ld.acquire.gpu.global.u32 %0, [%1];" : "=r"(gen) : "l"(&g_sync_gen));
        unsigned arrived = atomicAdd(&g_sync_count, 1);
        if (arrived == NCTA - 1) {
            atomicExch(&g_sync_count, 0);
            __threadfence();
            atomicAdd(&g_sync_gen, 1);
        } else {
            unsigned cur;
            do {
                __nanosleep(20);
                asm volatile("ld.acquire.gpu.global.u32 %0, [%1];" : "=r"(cur) : "l"(&g_sync_gen));
            } while (cur == gen);
        }
        __threadfence();
    }
    __syncthreads();
}

#if HAS_TCGEN05
__device__ __forceinline__ uint64_t make_desc_sw128(uint32_t addr) {
    return 0x4000404000010000ULL | (uint64_t)((addr >> 4) & 0x3FFF);
}
__device__ __forceinline__ void mbar_init(uint32_t mbar, uint32_t cnt) {
    asm volatile("mbarrier.init.shared.b64 [%0], %1;" :: "r"(mbar), "r"(cnt) : "memory");
}
__device__ __forceinline__ void mbar_inval(uint32_t mbar) {
    asm volatile("mbarrier.inval.shared.b64 [%0];" :: "r"(mbar) : "memory");
}
__device__ __forceinline__ void mbar_wait(uint32_t mbar, uint32_t parity) {
    asm volatile(
        "{\n\t.reg .pred P1;\n\t"
        "WAIT_LOOP_%=:\n\t"
        "mbarrier.try_wait.parity.acquire.cta.shared::cta.b64 P1, [%0], %1, 0x989680;\n\t"
        "@P1 bra.uni WAIT_DONE_%=;\n\t"
        "bra.uni WAIT_LOOP_%=;\n\t"
        "WAIT_DONE_%=:\n\t}"
        :: "r"(mbar), "r"(parity) : "memory");
}
__device__ __forceinline__ void mbar_expect(uint32_t mbar, uint32_t bytes) {
    asm volatile("mbarrier.arrive.expect_tx.shared.b64 _, [%0], %1;"
                 :: "r"(mbar), "r"(bytes) : "memory");
}
__device__ __forceinline__ void tmem_alloc(uint32_t smem_res, uint32_t ncols) {
    asm volatile("tcgen05.alloc.cta_group::1.sync.aligned.shared::cta.b32 [%0], %1;"
                 :: "r"(smem_res), "r"(ncols) : "memory");
}
__device__ __forceinline__ void tmem_dealloc(uint32_t tmem, uint32_t ncols) {
    asm volatile("tcgen05.dealloc.cta_group::1.sync.aligned.b32 %0, %1;" :: "r"(tmem), "r"(ncols));
}
__device__ __forceinline__ void tmem_relinquish() {
    asm volatile("tcgen05.relinquish_alloc_permit.cta_group::1.sync.aligned;");
}
__device__ __forceinline__ void tc_commit(uint32_t mbar) {
    asm volatile("tcgen05.commit.cta_group::1.mbarrier::arrive::one.shared::cluster.b64 [%0];"
                 :: "r"(mbar) : "memory");
}
__device__ __forceinline__ void tc_commit_mc(uint32_t mbar, uint16_t mask) {
    asm volatile(
        "tcgen05.commit.cta_group::1.mbarrier::arrive::one.shared::cluster.multicast::cluster.b64 [%0], %1;"
        :: "r"(mbar), "h"(mask) : "memory");
}
__device__ __forceinline__ void tc_fence_after() {
    asm volatile("tcgen05.fence::after_thread_sync;" ::: "memory");
}
__device__ __forceinline__ void tc_fence_before() {
    asm volatile("tcgen05.fence::before_thread_sync;" ::: "memory");
}
__device__ __forceinline__ void tc_wait_ld() {
    asm volatile("tcgen05.wait::ld.sync.aligned;" ::: "memory");
}
__device__ __forceinline__ void fence_proxy_async_shared() {
    asm volatile("fence.proxy.async.shared::cta;" ::: "memory");
}
__device__ __forceinline__ void mma_f16_ss(uint32_t d_tmem, uint64_t a_desc, uint64_t b_desc,
                                           uint32_t idesc, uint32_t enable) {
    asm volatile(
        "{\n\t.reg .pred p;\n\t"
        "setp.ne.u32 p, %4, 0;\n\t"
        "tcgen05.mma.cta_group::1.kind::f16 [%0], %1, %2, %3, {%5, %5, %5, %5}, p;\n\t}"
        :: "r"(d_tmem), "l"(a_desc), "l"(b_desc), "r"(idesc), "r"(enable), "r"(0u)
        : "memory");
}
__device__ __forceinline__ void tma_mc(uint32_t dst, const CUtensorMap* m, int cx, int cy,
                                       uint32_t mbar, uint16_t mask) {
    asm volatile(
        "cp.async.bulk.tensor.2d.shared::cluster.global.tile.mbarrier::complete_tx::bytes.multicast::cluster "
        "[%0], [%1, {%2, %3}], [%4], %5;"
        :: "r"(dst), "l"(m), "r"(cx), "r"(cy), "r"(mbar), "h"(mask) : "memory");
}
__device__ __forceinline__ void cp16(uint32_t dst, const void* src) {
    asm volatile("cp.async.cg.shared.global [%0], [%1], 16;" :: "r"(dst), "l"(src));
}
__device__ __forceinline__ void cp_commit() {
    asm volatile("cp.async.commit_group;" ::: "memory");
}
#define CP_WAIT_GROUP(n) asm volatile("cp.async.wait_group %0;" :: "n"(n) : "memory")
#define CLUSTER_SYNC_() do { \
    asm volatile("barrier.cluster.arrive.aligned;" ::: "memory"); \
    asm volatile("barrier.cluster.wait.aligned;" ::: "memory"); \
} while (0)
#define TC_LD_X16(r, tmem_addr) \
    asm volatile( \
        "tcgen05.ld.sync.aligned.32x32b.x16.b32 " \
        "{%0, %1, %2, %3, %4, %5, %6, %7, " \
        " %8, %9, %10, %11, %12, %13, %14, %15}, [%16];" \
        : "=r"((r)[0]),  "=r"((r)[1]),  "=r"((r)[2]),  "=r"((r)[3]), \
          "=r"((r)[4]),  "=r"((r)[5]),  "=r"((r)[6]),  "=r"((r)[7]), \
          "=r"((r)[8]),  "=r"((r)[9]),  "=r"((r)[10]), "=r"((r)[11]), \
          "=r"((r)[12]), "=r"((r)[13]), "=r"((r)[14]), "=r"((r)[15]) \
        : "r"(tmem_addr))
#define TC_LD_X32(r, tmem_addr) \
    asm volatile( \
        "tcgen05.ld.sync.aligned.32x32b.x32.b32 " \
        "{%0, %1, %2, %3, %4, %5, %6, %7, " \
        " %8, %9, %10, %11, %12, %13, %14, %15, " \
        " %16, %17, %18, %19, %20, %21, %22, %23, " \
        " %24, %25, %26, %27, %28, %29, %30, %31}, [%32];" \
        : "=r"((r)[0]),  "=r"((r)[1]),  "=r"((r)[2]),  "=r"((r)[3]), \
          "=r"((r)[4]),  "=r"((r)[5]),  "=r"((r)[6]),  "=r"((r)[7]), \
          "=r"((r)[8]),  "=r"((r)[9]),  "=r"((r)[10]), "=r"((r)[11]), \
          "=r"((r)[12]), "=r"((r)[13]), "=r"((r)[14]), "=r"((r)[15]), \
          "=r"((r)[16]), "=r"((r)[17]), "=r"((r)[18]), "=r"((r)[19]), \
          "=r"((r)[20]), "=r"((r)[21]), "=r"((r)[22]), "=r"((r)[23]), \
          "=r"((r)[24]), "=r"((r)[25]), "=r"((r)[26]), "=r"((r)[27]), \
          "=r"((r)[28]), "=r"((r)[29]), "=r"((r)[30]), "=r"((r)[31]) \
        : "r"(tmem_addr))
#endif  // HAS_TCGEN05

#define IDESC_N128 ((1u << 4) | (1u << 7) | (1u << 10) | (16u << 17) | (8u << 24))
#define IDESC_N64  ((1u << 4) | (1u << 7) | (1u << 10) | (8u << 17)  | (8u << 24))

#define LSTG 49152
#define L_A_HI 0
#define L_A_LO 16384
#define L_B_HI 32768
#define L_B_LO 40960
#define NST 4
#define SMEM_LSTM (1024 + NST * LSTG)

#define STAGE_BYTES 65536
#define OFF_A_HI 0
#define OFF_A_LO 16384
#define OFF_B_HI 32768
#define OFF_B_LO 49152
#define HW2_BASE   1024
#define HSTAGE0    33792
#define SMEM_HEAD  (HSTAGE0 + 3 * STAGE_BYTES)

// ---------------- prep ----------------
__global__ void prep_misc(const float* __restrict__ Wd, const float* __restrict__ W2) {
    for (int i = blockIdx.x * blockDim.x + threadIdx.x; i < B_ * H_;
         i += gridDim.x * blockDim.x) {
        g_c[i] = 0.f;
        g_hall_hi[i] = __float2bfloat16(0.f);
        g_hall_lo[i] = __float2bfloat16(0.f);
        if (i < HEAD_ * H_) {
            float v = Wd[i];
            __nv_bfloat16 hi = __float2bfloat16(v);
            g_Wd_hi[i] = hi;
            g_Wd_lo[i] = __float2bfloat16(v - __bfloat162float(hi));
        }
        if (i < OUT_ * HEAD_) {
            float v = W2[i];
            __nv_bfloat16 hi = __float2bfloat16(v);
            g_W2_hi[i] = hi;
            g_W2_lo[i] = __float2bfloat16(v - __bfloat162float(hi));
        }
        if (i < NCTA * 32) g_arr[i] = 0;
        if (i == 0) { g_sync_count = 0; g_sync_gen = 0; g_rel = 0; }
    }
}
// row' = ntile*64 + gate*16 + unit  <-  orig row gate*1024 + ntile*16 + unit
__global__ void prep_w(const float* __restrict__ Wih, const float* __restrict__ Whh) {
    const size_t n = (size_t)G4 * KTOT;
    for (size_t i = blockIdx.x * blockDim.x + threadIdx.x; i < n;
         i += (size_t)gridDim.x * blockDim.x) {
        int rp = (int)(i / KTOT);
        int k = (int)(i - (size_t)rp * KTOT);
        int ntile = rp >> 6;
        int g = (rp & 63) >> 4;
        int u = rp & 15;
        int orow = (g << 10) + (ntile << 4) + u;
        float v = (k < IN_) ? Wih[(size_t)orow * IN_ + k] : Whh[(size_t)orow * H_ + (k - IN_)];
        __nv_bfloat16 hi = __float2bfloat16(v);
        g_Wr_hi[i] = hi;
        g_Wr_lo[i] = __float2bfloat16(v - __bfloat162float(hi));
    }
}
__global__ void prep_x(const float* __restrict__ x) {
    const size_t n = (size_t)S_ * B_ * IN_;
    for (size_t i = blockIdx.x * blockDim.x + threadIdx.x; i < n;
         i += (size_t)gridDim.x * blockDim.x) {
        int t = (int)(i / (B_ * IN_));
        int rem = (int)(i - (size_t)t * (B_ * IN_));
        int b = rem / IN_;
        int ii = rem - b * IN_;
        float v = x[((size_t)b * S_ + t) * IN_ + ii];
        __nv_bfloat16 hi = __float2bfloat16(v);
        g_x_hi[i] = hi;
        g_x_lo[i] = __float2bfloat16(v - __bfloat162float(hi));
    }
}

// ---------------- persistent LSTM: clusters of 4, TMA, c-in-registers, dist barrier ----
__global__ void __launch_bounds__(256, 1) __cluster_dims__(4, 1, 1) lstm_persist(
    const float* __restrict__ bih, const float* __restrict__ bhh,
    const __grid_constant__ CUtensorMap mXh, const __grid_constant__ CUtensorMap mXl,
    const __grid_constant__ CUtensorMap mAh, const __grid_constant__ CUtensorMap mAl,
    const __grid_constant__ CUtensorMap mWh, const __grid_constant__ CUtensorMap mWl)
{
#if HAS_TCGEN05
    extern __shared__ char smem[];
    const uint32_t sb = smem_u32(smem);
    const int tid = threadIdx.x;
    const int wid = tid >> 5;
    const int lane = tid & 31;
    const int rank = blockIdx.x & 3;
    const int bm0 = (rank & 1) * 128;
    const int ntile = (blockIdx.x >> 2) * 2 + (rank >> 1);
    const int j0 = ntile * UNITS;

    if (wid == 0) { tmem_alloc(sb, 128); tmem_relinquish(); }
    if (tid == 0) {
#pragma unroll
        for (int s = 0; s < NST; s++) {
            mbar_init(sb + 8 + 8 * s, 1);          // full[s]: 1 expect_tx arrive
            mbar_init(sb + 40 + 8 * s, 4);         // empty[s]: 4 multicast commits
        }
    }
    if (tid < 64) {
        int grow = ((tid >> 4) << 10) + j0 + (tid & 15);
        ((float*)(smem + 256))[tid] = bih[grow] + bhh[grow];
    }
    __syncthreads();
    CLUSTER_SYNC_();
    const uint32_t tmem = *(const uint32_t*)smem;

    uint64_t dAh[NST], dAl[NST], dBh[NST], dBl[NST];
#pragma unroll
    for (int s = 0; s < NST; s++) {
        uint32_t st = sb + 1024 + s * LSTG;
        dAh[s] = make_desc_sw128(st + L_A_HI);
        dAl[s] = make_desc_sw128(st + L_A_LO);
        dBh[s] = make_desc_sw128(st + L_B_HI);
        dBl[s] = make_desc_sw128(st + L_B_LO);
    }

    auto issue_load = [&](int cn, int sl, int tt) {
        const uint32_t st = sb + 1024 + sl * LSTG;
        const uint32_t fm = sb + 8 + 8 * sl;
        mbar_expect(fm, 49152);
        if (rank == 1 || rank == 2) {
            const uint16_t mask = (rank == 1) ? 0xA : 0x5;
            if (cn == 0) {
                tma_mc(st + L_A_HI, &mXh, 0, tt * B_ + bm0, fm, mask);
                tma_mc(st + L_A_LO, &mXl, 0, tt * B_ + bm0, fm, mask);
            } else {
                tma_mc(st + L_A_HI, &mAh, (cn - 1) * KC, tt * B_ + bm0, fm, mask);
                tma_mc(st + L_A_LO, &mAl, (cn - 1) * KC, tt * B_ + bm0, fm, mask);
            }
        } else {
            const uint16_t mask = (rank == 0) ? 0x3 : 0xC;
            tma_mc(st + L_B_HI, &mWh, cn * KC, ntile * 64, fm, mask);
            tma_mc(st + L_B_LO, &mWl, cn * KC, ntile * 64, fm, mask);
        }
    };

    uint32_t pf[NST] = {0, 0, 0, 0};
    uint32_t pe[NST] = {0, 0, 0, 0};

    // persistent cell state: each epilogue thread owns rows (bm0+wid*32+lane), units 0..15
    float creg[16];
#pragma unroll
    for (int u = 0; u < 16; u++) creg[u] = 0.f;

    for (int t = 0; t < S_; t++) {
        if (t == 0 && tid == 0) {
            issue_load(0, 0, 0); issue_load(1, 1, 0); issue_load(2, 2, 0);
        }
#pragma unroll
        for (int ck = 0; ck < NCHUNK; ck++) {
            const int s = ck & 3;
            if (tid == 0) {
                mbar_wait(sb + 8 + 8 * s, pf[s]); pf[s] ^= 1;
#pragma unroll
                for (int k4 = 0; k4 < 4; k4++) {
                    uint32_t en0 = (ck > 0 || k4 > 0) ? 1u : 0u;
                    mma_f16_ss(tmem, dAh[s] + k4 * 2, dBh[s] + k4 * 2, IDESC_N64, en0);
                    mma_f16_ss(tmem, dAh[s] + k4 * 2, dBl[s] + k4 * 2, IDESC_N64, 1u);
                    mma_f16_ss(tmem, dAl[s] + k4 * 2, dBh[s] + k4 * 2, IDESC_N64, 1u);
                }
                tc_commit_mc(sb + 40 + 8 * s, 0xF);
            }
            const int cn = ck + 3;
            if (cn <= NCHUNK - 1) {
                const int sl = cn & 3;
                if (cn >= 4) {
                    if (tid == 0) mbar_wait(sb + 40 + 8 * sl, pe[sl]);
                    pe[sl] ^= 1;
                }
                if (tid == 0) issue_load(cn, sl, t);
            }
        }
        // drain: only tid0 (phase-exact) waits; barrier releases the rest
        if (tid == 0) mbar_wait(sb + 40, pe[0]);
        pe[0] ^= 1;
        pe[1] ^= 1; pe[2] ^= 1; pe[3] ^= 1;
        __syncthreads();
        tc_fence_after();

        if (t + 1 < S_ && tid == 0) issue_load(0, 0, t + 1);   // x-only, stage0 free

        // ---- epilogue: c in registers, h -> global hi/lo ----
        if (wid < 4) {
            const int brow = bm0 + wid * 32 + lane;
            const size_t hbase = ((size_t)(t + 1) * B_ + brow) * H_ + j0;
            const float* bs = (const float*)(smem + 256);
            uint32_t ri[16], rf[16], rg[16], ro[16];
            TC_LD_X16(ri, tmem + 0);
            TC_LD_X16(rf, tmem + 16);
            TC_LD_X16(rg, tmem + 32);
            TC_LD_X16(ro, tmem + 48);
            tc_wait_ld();

            float hnv[16];
#pragma unroll
            for (int u = 0; u < 16; u++) {
                float ig = __uint_as_float(ri[u]) + bs[u];
                float fg = __uint_as_float(rf[u]) + bs[16 + u];
                float gg = __uint_as_float(rg[u]) + bs[32 + u];
                float og = __uint_as_float(ro[u]) + bs[48 + u];
                float cn = sigf(fg) * creg[u] + sigf(ig) * tanhfast(gg);
                creg[u] = cn;
                hnv[u] = sigf(og) * tanhfast(cn);
            }
            uint32_t hp[8], lp[8];
#pragma unroll
            for (int v = 0; v < 8; v++) {
                __nv_bfloat16 h0 = __float2bfloat16(hnv[v * 2]);
                __nv_bfloat16 h1 = __float2bfloat16(hnv[v * 2 + 1]);
                __nv_bfloat16 l0 = __float2bfloat16(hnv[v * 2] - __bfloat162float(h0));
                __nv_bfloat16 l1 = __float2bfloat16(hnv[v * 2 + 1] - __bfloat162float(h1));
                hp[v] = ((uint32_t)__bfloat16_as_ushort(h1) << 16) | __bfloat16_as_ushort(h0);
                lp[v] = ((uint32_t)__bfloat16_as_ushort(l1) << 16) | __bfloat16_as_ushort(l0);
            }
            *(uint4*)(&g_hall_hi[hbase])     = make_uint4(hp[0], hp[1], hp[2], hp[3]);
            *(uint4*)(&g_hall_hi[hbase + 8]) = make_uint4(hp[4], hp[5], hp[6], hp[7]);
            *(uint4*)(&g_hall_lo[hbase])     = make_uint4(lp[0], lp[1], lp[2], lp[3]);
            *(uint4*)(&g_hall_lo[hbase + 8]) = make_uint4(lp[4], lp[5], lp[6], lp[7]);
            tc_fence_before();
        }

        // ---- distributed grid barrier (arrival flags + single release word) ----
        if (t + 1 < S_) {
            __syncthreads();
            const unsigned v = (unsigned)(t + 1);
            if (tid == 0) {
                __threadfence();
                asm volatile("st.release.gpu.global.u32 [%0], %1;"
                             :: "l"(&g_arr[blockIdx.x * 32]), "r"(v) : "memory");
            }
            if (blockIdx.x == 0) {
                if (tid < NCTA) {
                    unsigned cur;
                    while (true) {
                        asm volatile("ld.acquire.gpu.global.u32 %0, [%1];"
                                     : "=r"(cur) : "l"(&g_arr[tid * 32]));
                        if (cur >= v) break;
                        __nanosleep(20);
                    }
                }
                __syncthreads();
                if (tid == 0)
                    asm volatile("st.release.gpu.global.u32 [%0], %1;"
                                 :: "l"(&g_rel), "r"(v) : "memory");
            } else {
                if (tid == 0) {
                    unsigned cur;
                    while (true) {
                        asm volatile("ld.acquire.gpu.global.u32 %0, [%1];"
                                     : "=r"(cur) : "l"(&g_rel));
                        if (cur >= v) break;
                        __nanosleep(20);
                    }
                }
                __syncthreads();
            }
            if (tid == 0) { issue_load(1, 1, t + 1); issue_load(2, 2, t + 1); }
        } else {
            __syncthreads();
        }
    }

    __syncthreads();
    CLUSTER_SYNC_();
    if (tid == 0) {
#pragma unroll
        for (int s = 0; s < NST; s++) { mbar_inval(sb + 8 + 8 * s); mbar_inval(sb + 40 + 8 * s); }
    }
    __syncthreads();
    if (wid == 0) tmem_dealloc(tmem, 128);
    CLUSTER_SYNC_();
#else
    // correct SIMT fallback (never runs on GB300)
    const int tid = threadIdx.x;
    const int rank = blockIdx.x & 3;
    const int bm0 = (rank & 1) * 128;
    const int ntile = (blockIdx.x >> 2) * 2 + (rank >> 1);
    const int j0 = ntile * UNITS;
    for (int t = 0; t < S_; t++) {
        for (int o = tid; o < 128 * UNITS; o += 256) {
            int row = o / UNITS, u = o % UNITS;
            int b = bm0 + row, jg = j0 + u;
            float acc[4] = {0.f, 0.f, 0.f, 0.f};
            for (int k = 0; k < KTOT; k++) {
                float a;
                if (k < IN_) {
                    size_t xo = ((size_t)t * B_ + b) * IN_ + k;
                    a = __bfloat162float(g_x_hi[xo]) + __bfloat162float(g_x_lo[xo]);
                } else {
                    size_t ho = ((size_t)t * B_ + b) * H_ + (k - IN_);
                    a = __bfloat162float(g_hall_hi[ho]) + __bfloat162float(g_hall_lo[ho]);
                }
#pragma unroll
                for (int g = 0; g < 4; g++) {
                    size_t wi = (size_t)(ntile * 64 + g * 16 + u) * KTOT + k;
                    acc[g] += a * (__bfloat162float(g_Wr_hi[wi]) + __bfloat162float(g_Wr_lo[wi]));
                }
            }
            float ig = acc[0] + bih[jg] + bhh[jg];
            float fg = acc[1] + bih[H_ + jg] + bhh[H_ + jg];
            float gg = acc[2] + bih[2 * H_ + jg] + bhh[2 * H_ + jg];
            float og = acc[3] + bih[3 * H_ + jg] + bhh[3 * H_ + jg];
            int idx = b * H_ + jg;
            float cn = sigf(fg) * g_c[idx] + sigf(ig) * tanhfast(gg);
            float hn = sigf(og) * tanhfast(cn);
            g_c[idx] = cn;
            size_t hb = ((size_t)(t + 1) * B_ + b) * H_ + jg;
            __nv_bfloat16 hh = __float2bfloat16(hn);
            g_hall_hi[hb] = hh;
            g_hall_lo[hb] = __float2bfloat16(hn - __bfloat162float(hh));
        }
        grid_sync();
    }
#endif
}

// ---------------- fused tcgen05 dense head (R9, passing) ----------------
__global__ void __launch_bounds__(256, 1) head_tc(
    const float* __restrict__ bd, const float* __restrict__ b2, float* __restrict__ out)
{
#if HAS_TCGEN05
    extern __shared__ char smem[];
    const uint32_t sb = smem_u32(smem);
    const int tid = threadIdx.x;
    const int wid = tid >> 5;
    const int lane = tid & 31;
    const int r0 = blockIdx.x * 128;

    if (wid == 0) { tmem_alloc(sb, 256); tmem_relinquish(); }
    if (tid == 0) { mbar_init(sb + 8, 1); mbar_init(sb + 16, 1); mbar_init(sb + 24, 1); }
    if (tid < 128) ((float*)(smem + 256))[tid] = bd[tid];
    if (tid < 64)  ((float*)(smem + 768))[tid] = b2[tid];
    for (int i = tid; i < 64 * 16; i += 256) {
        int row = i >> 4;
        int col = (i & 15) * 8;
        int chunk = col >> 6, kin = col & 63;
        uint32_t off = row * 128 + kin * 2;
        uint32_t sw = off ^ ((off >> 3) & 0x70);
        *(uint4*)(smem + HW2_BASE + chunk * 8192 + sw) =
            *(const uint4*)(g_W2_hi + row * HEAD_ + col);
        *(uint4*)(smem + HW2_BASE + 16384 + chunk * 8192 + sw) =
            *(const uint4*)(g_W2_lo + row * HEAD_ + col);
    }
    __syncthreads();
    const uint32_t tmem = *(const uint32_t*)smem;

    auto load_chunk = [&](int cn, int buf) {
        const uint32_t st = sb + HSTAGE0 + buf * STAGE_BYTES;
#pragma unroll
        for (int q = 0; q < 4; q++) {
            int slot = tid + q * 256;
            int row = slot >> 3, cc = slot & 7;
            uint32_t off = row * 128 + cc * 16;
            uint32_t sw = off ^ ((off >> 3) & 0x70);
            size_t oa = ((size_t)(B_ + r0 + row)) * H_ + cn * KC + cc * 8;
            cp16(st + OFF_A_HI + sw, g_hall_hi + oa);
            cp16(st + OFF_A_LO + sw, g_hall_lo + oa);
            size_t ob = (size_t)row * H_ + cn * KC + cc * 8;
            cp16(st + OFF_B_HI + sw, g_Wd_hi + ob);
            cp16(st + OFF_B_LO + sw, g_Wd_lo + ob);
        }
        cp_commit();
    };

    uint32_t wp[3] = {0, 0, 0};
    load_chunk(0, 0);
    load_chunk(1, 1);
#pragma unroll
    for (int ck = 0; ck < 16; ck++) {
        const int cn = ck + 2;
        if (cn <= 15) {
            const int b = cn % 3;
            if (cn >= 3) { mbar_wait(sb + 8 + 8 * b, wp[b]); wp[b] ^= 1; }
            load_chunk(cn, b);
        }
        if (ck <= 13)      CP_WAIT_GROUP(2);
        else if (ck == 14) CP_WAIT_GROUP(1);
        else               CP_WAIT_GROUP(0);
        __syncthreads();
        if (tid == 0) {
            const uint32_t st = sb + HSTAGE0 + (ck % 3) * STAGE_BYTES;
            fence_proxy_async_shared();
            uint64_t dAh = make_desc_sw128(st + OFF_A_HI);
            uint64_t dAl = make_desc_sw128(st + OFF_A_LO);
            uint64_t dBh = make_desc_sw128(st + OFF_B_HI);
            uint64_t dBl = make_desc_sw128(st + OFF_B_LO);
#pragma unroll
            for (int k4 = 0; k4 < 4; k4++) {
                uint32_t en0 = (ck > 0 || k4 > 0) ? 1u : 0u;
                mma_f16_ss(tmem, dAh + k4 * 2, dBh + k4 * 2, IDESC_N128, en0);
                mma_f16_ss(tmem, dAh + k4 * 2, dBl + k4 * 2, IDESC_N128, 1u);
                mma_f16_ss(tmem, dAl + k4 * 2, dBh + k4 * 2, IDESC_N128, 1u);
            }
            tc_commit(sb + 8 + 8 * (ck % 3));
        }
    }
    mbar_wait(sb + 8, wp[0]); wp[0] ^= 1;
    wp[1] ^= 1; wp[2] ^= 1;
    tc_fence_after();

    if (wid < 4) {
        const int rowl = wid * 32 + lane;
        const float* bds = (const float*)(smem + 256);
#pragma unroll
        for (int cb = 0; cb < 4; cb++) {
            uint32_t r[32];
            TC_LD_X32(r, tmem + cb * 32);
            tc_wait_ld();
#pragma unroll
            for (int c = 0; c < 32; c++) {
                int col = cb * 32 + c;
                float v = __uint_as_float(r[c]) + bds[col];
                v = fmaxf(v, 0.f);
                __nv_bfloat16 hi = __float2bfloat16(v);
                __nv_bfloat16 lo = __float2bfloat16(v - __bfloat162float(hi));
                int chunk = col >> 6, kin = col & 63;
                uint32_t off = rowl * 128 + kin * 2;
                uint32_t sw = off ^ ((off >> 3) & 0x70);
                *(__nv_bfloat16*)(smem + HSTAGE0 + chunk * 16384 + sw) = hi;
                *(__nv_bfloat16*)(smem + HSTAGE0 + 32768 + chunk * 16384 + sw) = lo;
            }
        }
        tc_fence_before();
    }
    __syncthreads();

    if (tid == 0) {
        fence_proxy_async_shared();
#pragma unroll
        for (int c = 0; c < 2; c++) {
            uint64_t dPh = make_desc_sw128(sb + HSTAGE0 + c * 16384);
            uint64_t dPl = make_desc_sw128(sb + HSTAGE0 + 32768 + c * 16384);
            uint64_t dWh = make_desc_sw128(sb + HW2_BASE + c * 8192);
            uint64_t dWl = make_desc_sw128(sb + HW2_BASE + 16384 + c * 8192);
#pragma unroll
            for (int k4 = 0; k4 < 4; k4++) {
                uint32_t en0 = (c > 0 || k4 > 0) ? 1u : 0u;
                mma_f16_ss(tmem + 128, dPh + k4 * 2, dWh + k4 * 2, IDESC_N64, en0);
                mma_f16_ss(tmem + 128, dPh + k4 * 2, dWl + k4 * 2, IDESC_N64, 1u);
                mma_f16_ss(tmem + 128, dPl + k4 * 2, dWh + k4 * 2, IDESC_N64, 1u);
            }
        }
        tc_commit(sb + 8);
    }
    mbar_wait(sb + 8, wp[0]); wp[0] ^= 1;
    tc_fence_after();

    if (wid < 4) {
        uint32_t d[64];
        TC_LD_X32(d, tmem + 128);
        TC_LD_X32(d + 32, tmem + 160);
        tc_wait_ld();
        tc_fence_before();
        const float* b2s = (const float*)(smem + 768);
        int r = r0 + wid * 32 + lane;
        int tt = r >> 8;
        int b = r & 255;
        float* op = out + ((size_t)b * S_ + tt) * OUT_;
#pragma unroll
        for (int v = 0; v < 16; v++) {
            *(float4*)(op + v * 4) = make_float4(
                __uint_as_float(d[v * 4 + 0]) + b2s[v * 4 + 0],
                __uint_as_float(d[v * 4 + 1]) + b2s[v * 4 + 1],
                __uint_as_float(d[v * 4 + 2]) + b2s[v * 4 + 2],
                __uint_as_float(d[v * 4 + 3]) + b2s[v * 4 + 3]);
        }
    }
    __syncthreads();
    if (tid == 0) { mbar_inval(sb + 8); mbar_inval(sb + 16); mbar_inval(sb + 24); }
    __syncthreads();
    if (wid == 0) tmem_dealloc(tmem, 256);
#else
    const int tid = threadIdx.x;
    const int r0 = blockIdx.x * 128;
    for (int rl = tid; rl < 128; rl += 256) {
        int r = r0 + rl;
        float p[HEAD_];
        for (int n = 0; n < HEAD_; n++) {
            float acc = bd[n];
            for (int k = 0; k < H_; k++) {
                size_t ho = ((size_t)(B_ + r)) * H_ + k;
                float hv = __bfloat162float(g_hall_hi[ho]) + __bfloat162float(g_hall_lo[ho]);
                float wv = __bfloat162float(g_Wd_hi[n * H_ + k]) +
                           __bfloat162float(g_Wd_lo[n * H_ + k]);
                acc += hv * wv;
            }
            p[n] = acc > 0.f ? acc : 0.f;
        }
        int tt = r >> 8, b = r & 255;
        for (int n = 0; n < OUT_; n++) {
            float acc = b2[n];
            for (int k = 0; k < HEAD_; k++) {
                float wv = __bfloat162float(g_W2_hi[n * HEAD_ + k]) +
                           __bfloat162float(g_W2_lo[n * HEAD_ + k]);
                acc += p[k] * wv;
            }
            out[((size_t)b * S_ + tt) * OUT_ + n] = acc;
        }
    }
#endif
}

// ---------------- host: tensormap building + launch ----------------
typedef CUresult (*EncodeFn)(CUtensorMap*, CUtensorMapDataType, cuuint32_t, void*,
    const cuuint64_t*, const cuuint64_t*, const cuuint32_t*, const cuuint32_t*,
    CUtensorMapInterleave, CUtensorMapSwizzle, CUtensorMapL2promotion, CUtensorMapFloatOOBfill);

static void make_map2d(EncodeFn enc, CUtensorMap* m, void* base, uint64_t d0, uint64_t d1,
                       uint64_t stride1, uint32_t b0, uint32_t b1) {
    cuuint64_t dims[2] = {d0, d1};
    cuuint64_t strides[1] = {stride1};
    cuuint32_t box[2] = {b0, b1};
    cuuint32_t es[2] = {1, 1};
    enc(m, CU_TENSOR_MAP_DATA_TYPE_BFLOAT16, 2, base, dims, strides, box, es,
        CU_TENSOR_MAP_INTERLEAVE_NONE, CU_TENSOR_MAP_SWIZZLE_128B,
        CU_TENSOR_MAP_L2_PROMOTION_L2_128B, CU_TENSOR_MAP_FLOAT_OOB_FILL_NONE);
}

extern "C" void kernel_launch(void* const* d_in, const int* in_sizes, int n_in,
                              void* d_out, int out_size)
{
    const float* x   = (const float*)d_in[0];
    const float* Wih = (const float*)d_in[1];
    const float* bih = (const float*)d_in[2];
    const float* Whh = (const float*)d_in[3];
    const float* bhh = (const float*)d_in[4];
    const float* Wd  = (const float*)d_in[5];
    const float* bd  = (const float*)d_in[6];
    const float* W2  = (const float*)d_in[7];
    const float* b2  = (const float*)d_in[8];
    float* out = (float*)d_out;

    cudaFuncSetAttribute(lstm_persist, cudaFuncAttributeMaxDynamicSharedMemorySize, SMEM_LSTM);
    cudaFuncSetAttribute(head_tc, cudaFuncAttributeMaxDynamicSharedMemorySize, SMEM_HEAD);

    EncodeFn enc = nullptr;
    {
        void* p = nullptr;
        cudaDriverEntryPointQueryResult qr;
        cudaGetDriverEntryPoint("cuTensorMapEncodeTiled", &p, cudaEnableDefault, &qr);
        enc = (EncodeFn)p;
    }
    void *pXh, *pXl, *pAh, *pAl, *pWh, *pWl;
    cudaGetSymbolAddress(&pXh, g_x_hi);
    cudaGetSymbolAddress(&pXl, g_x_lo);
    cudaGetSymbolAddress(&pAh, g_hall_hi);
    cudaGetSymbolAddress(&pAl, g_hall_lo);
    cudaGetSymbolAddress(&pWh, g_Wr_hi);
    cudaGetSymbolAddress(&pWl, g_Wr_lo);

    CUtensorMap mXh, mXl, mAh, mAl, mWh, mWl;
    make_map2d(enc, &mXh, pXh, IN_, (uint64_t)S_ * B_, IN_ * 2, 64, 128);
    make_map2d(enc, &mXl, pXl, IN_, (uint64_t)S_ * B_, IN_ * 2, 64, 128);
    make_map2d(enc, &mAh, pAh, H_, (uint64_t)(S_ + 1) * B_, H_ * 2, 64, 128);
    make_map2d(enc, &mAl, pAl, H_, (uint64_t)(S_ + 1) * B_, H_ * 2, 64, 128);
    make_map2d(enc, &mWh, pWh, KTOT, G4, KTOT * 2, 64, 64);
    make_map2d(enc, &mWl, pWl, KTOT, G4, KTOT * 2, 64, 64);

    prep_misc<<<512, 256>>>(Wd, W2);
    prep_w<<<512, 256>>>(Wih, Whh);
    prep_x<<<512, 256>>>(x);

    lstm_persist<<<NCTA, 256, SMEM_LSTM>>>(bih, bhh, mXh, mXl, mAh, mAl, mWh, mWl);
    head_tc<<<(S_ * B_) / 128, 256, SMEM_HEAD>>>(bd, b2, out);
}